// round 10
// baseline (speedup 1.0000x reference)
#include <cuda_runtime.h>
#include <cuda_fp16.h>
#include <math.h>
#include <stdint.h>

#define BB   64
#define TT   4096
#define HID  1024
#define MEM  1024
#define ATTN 256
#define TCH  16          // ctx t-chunks

// ---------------- device scratch ----------------
__device__ float g_q[BB * ATTN];
__device__ float g_e[BB * TT];
__device__ float g_ctx[TCH * BB * MEM];

// ---------------- helpers ----------------
__device__ __forceinline__ void cp_async16(void* smem, const void* gmem) {
    unsigned s = (unsigned)__cvta_generic_to_shared(smem);
    asm volatile("cp.async.cg.shared.global [%0], [%1], 16;\n" :: "r"(s), "l"(gmem));
}
__device__ __forceinline__ void cp_commit() {
    asm volatile("cp.async.commit_group;\n");
}
template<int N>
__device__ __forceinline__ void cp_wait() {
    asm volatile("cp.async.wait_group %0;\n" :: "n"(N));
}
__device__ __forceinline__ uint32_t pack_h2(float x, float y) {
    uint32_t r;
    asm("cvt.rn.f16x2.f32 %0, %2, %1;" : "=r"(r) : "f"(x), "f"(y));
    return r;   // lo = x, hi = y
}
__device__ __forceinline__ void mma_f16(float* c, const uint32_t* a, const uint32_t* b) {
    asm volatile(
        "mma.sync.aligned.m16n8k16.row.col.f32.f16.f16.f32 "
        "{%0,%1,%2,%3}, {%4,%5,%6,%7}, {%8,%9}, {%0,%1,%2,%3};"
        : "+f"(c[0]), "+f"(c[1]), "+f"(c[2]), "+f"(c[3])
        : "r"(a[0]), "r"(a[1]), "r"(a[2]), "r"(a[3]), "r"(b[0]), "r"(b[1]));
}
__device__ __forceinline__ float tanh_acc(float x) {
    float e2 = __expf(2.0f * x);
    return 1.0f - __fdividef(2.0f, e2 + 1.0f);
}

// ---------------- kernel 1: q = h_t @ w_h^T  [64,256] ----------------
__global__ void q_kernel(const float* __restrict__ h_t, const float* __restrict__ w_h) {
    int g = blockIdx.x * 8 + (threadIdx.x >> 5);
    int lane = threadIdx.x & 31;
    int b = g >> 8, a = g & 255;
    const float4* hp = (const float4*)(h_t + (size_t)b * HID);
    const float4* wp = (const float4*)(w_h + (size_t)a * HID);
    float s = 0.f;
    #pragma unroll
    for (int i = lane; i < 256; i += 32) {
        float4 h4 = hp[i], w4 = wp[i];
        s += h4.x * w4.x + h4.y * w4.y + h4.z * w4.z + h4.w * w4.w;
    }
    #pragma unroll
    for (int o = 16; o > 0; o >>= 1) s += __shfl_xor_sync(0xffffffffu, s, o);
    if (lane == 0) g_q[b * ATTN + a] = s;
}

// ---------------- kernel 2: fused e-GEMM (fp16 mma, 64x256 tile, occ 2) ----------------
// CTA tile: 64 t-rows x 256 attn cols, K-chunks of 32, cp.async fp32 double buffer.
// 8 warps (2 x 4), warp tile 32x64 via m16n8k16; two CTAs resident per SM.
#define MT 64
#define AS_STRIDE 40
#define A_BUF (MT * AS_STRIDE)    // 2560 floats
#define B_BUF (256 * AS_STRIDE)   // 10240 floats
#define GEMM_SMEM_BYTES ((2 * A_BUF + 2 * B_BUF) * 4)   // 102,400 B

__global__ __launch_bounds__(256, 2)
void gemm_e_kernel(const float* __restrict__ memory, const float* __restrict__ w_m,
                   const float* __restrict__ v) {
    extern __shared__ float sm[];
    float* As = sm;               // [2][64][40]
    float* Bsm = sm + 2 * A_BUF;  // [2][256][40]
    __shared__ float q_s[ATTN];
    __shared__ float v_s[ATTN];
    __shared__ float e_s[4][MT];

    const int tid = threadIdx.x;
    const int b = blockIdx.y;
    const int t0 = blockIdx.x * MT;

    q_s[tid] = g_q[b * ATTN + tid];
    v_s[tid] = v[tid];

    const float* Ag = memory + ((size_t)b * TT + t0) * MEM;
    const float* Bg = w_m;

    auto stage = [&](int kc, int bf) {
        const float* ag = Ag + kc * 32;
        #pragma unroll
        for (int i = 0; i < 2; i++) {             // A: 64 rows x 8 x 16B
            int idx = i * 256 + tid;
            int r = idx >> 3, c = (idx & 7) * 4;
            cp_async16(&As[bf * A_BUF + r * AS_STRIDE + c], ag + (size_t)r * MEM + c);
        }
        const float* bg = Bg + kc * 32;
        #pragma unroll
        for (int i = 0; i < 8; i++) {             // B: 256 rows x 8 x 16B
            int idx = i * 256 + tid;
            int r = idx >> 3, c = (idx & 7) * 4;
            cp_async16(&Bsm[bf * B_BUF + r * AS_STRIDE + c], bg + (size_t)r * MEM + c);
        }
    };

    const int warp = tid >> 5, lane = tid & 31;
    const int wm = warp >> 2, wn = warp & 3;      // 2 x 4 warps, 32x64 warp tiles
    const int gid = lane >> 2, tig = lane & 3;

    float acc[2][8][4];
    #pragma unroll
    for (int mi = 0; mi < 2; mi++)
        #pragma unroll
        for (int ni = 0; ni < 8; ni++)
            #pragma unroll
            for (int j = 0; j < 4; j++) acc[mi][ni][j] = 0.f;

    int buf = 0;
    stage(0, 0);
    cp_commit();

    for (int kc = 0; kc < 32; kc++) {
        if (kc + 1 < 32) { stage(kc + 1, buf ^ 1); cp_commit(); cp_wait<1>(); }
        else             { cp_wait<0>(); }
        __syncthreads();

        const float* A = &As[buf * A_BUF];
        const float* Bs = &Bsm[buf * B_BUF];
        #pragma unroll
        for (int kw = 0; kw < 32; kw += 16) {
            uint32_t af[2][4], bf[8][2];
            #pragma unroll
            for (int mi = 0; mi < 2; mi++) {
                int r = wm * 32 + mi * 16 + gid;
                float2 f0 = *(const float2*)(A + r * AS_STRIDE + kw + 2 * tig);
                float2 f1 = *(const float2*)(A + (r + 8) * AS_STRIDE + kw + 2 * tig);
                float2 f2 = *(const float2*)(A + r * AS_STRIDE + kw + 2 * tig + 8);
                float2 f3 = *(const float2*)(A + (r + 8) * AS_STRIDE + kw + 2 * tig + 8);
                af[mi][0] = pack_h2(f0.x, f0.y);
                af[mi][1] = pack_h2(f1.x, f1.y);
                af[mi][2] = pack_h2(f2.x, f2.y);
                af[mi][3] = pack_h2(f3.x, f3.y);
            }
            #pragma unroll
            for (int ni = 0; ni < 8; ni++) {
                int c = wn * 64 + ni * 8 + gid;
                float2 f0 = *(const float2*)(Bs + c * AS_STRIDE + kw + 2 * tig);
                float2 f1 = *(const float2*)(Bs + c * AS_STRIDE + kw + 2 * tig + 8);
                bf[ni][0] = pack_h2(f0.x, f0.y);
                bf[ni][1] = pack_h2(f1.x, f1.y);
            }
            #pragma unroll
            for (int mi = 0; mi < 2; mi++)
                #pragma unroll
                for (int ni = 0; ni < 8; ni++)
                    mma_f16(acc[mi][ni], af[mi], bf[ni]);
        }
        __syncthreads();
        buf ^= 1;
    }

    // epilogue: e[t] = sum_a v[a] * tanh(q[a] + k[t][a])
    #pragma unroll
    for (int mi = 0; mi < 2; mi++) {
        float s0 = 0.f, s1 = 0.f;
        #pragma unroll
        for (int ni = 0; ni < 8; ni++) {
            int c0 = wn * 64 + ni * 8 + 2 * tig;
            s0 += v_s[c0]     * tanh_acc(q_s[c0]     + acc[mi][ni][0]);
            s0 += v_s[c0 + 1] * tanh_acc(q_s[c0 + 1] + acc[mi][ni][1]);
            s1 += v_s[c0]     * tanh_acc(q_s[c0]     + acc[mi][ni][2]);
            s1 += v_s[c0 + 1] * tanh_acc(q_s[c0 + 1] + acc[mi][ni][3]);
        }
        s0 += __shfl_xor_sync(0xffffffffu, s0, 1);
        s0 += __shfl_xor_sync(0xffffffffu, s0, 2);
        s1 += __shfl_xor_sync(0xffffffffu, s1, 1);
        s1 += __shfl_xor_sync(0xffffffffu, s1, 2);
        if (tig == 0) {
            e_s[wn][wm * 32 + mi * 16 + gid]     = s0;
            e_s[wn][wm * 32 + mi * 16 + gid + 8] = s1;
        }
    }
    __syncthreads();
    if (tid < MT) {
        float e = e_s[0][tid] + e_s[1][tid] + e_s[2][tid] + e_s[3][tid];
        g_e[(size_t)b * TT + t0 + tid] = e;
    }
}

// ---------------- kernel 3: masked softmax — UNCHANGED ----------------
__global__ void softmax_kernel(const void* __restrict__ maskp, float* __restrict__ out_attn) {
    const int b = blockIdx.x, tid = threadIdx.x;
    __shared__ int flag;
    __shared__ float red[8];
    if (tid == 0) flag = 0;
    __syncthreads();
    const int* mi32 = (const int*)maskp;
    if (tid < 64) {
        unsigned w = (unsigned)mi32[tid];
        if (w > 1u) atomicOr(&flag, 1);
    }
    __syncthreads();
    const bool bytes = (flag != 0);
    const unsigned char* mu8 = (const unsigned char*)maskp;

    float loc[16];
    float mx = -INFINITY;
    #pragma unroll
    for (int i = 0; i < 16; i++) {
        int t = i * 256 + tid;
        bool m = bytes ? (mu8[(size_t)b * TT + t] != 0) : (mi32[(size_t)b * TT + t] != 0);
        float e = m ? g_e[(size_t)b * TT + t] : -INFINITY;
        loc[i] = e;
        mx = fmaxf(mx, e);
    }
    int lane = tid & 31, wid = tid >> 5;
    #pragma unroll
    for (int o = 16; o > 0; o >>= 1) mx = fmaxf(mx, __shfl_xor_sync(0xffffffffu, mx, o));
    if (lane == 0) red[wid] = mx;
    __syncthreads();
    if (tid == 0) {
        float m = red[0];
        for (int i = 1; i < 8; i++) m = fmaxf(m, red[i]);
        red[0] = m;
    }
    __syncthreads();
    mx = red[0];

    float s = 0.f;
    #pragma unroll
    for (int i = 0; i < 16; i++) {
        float p = __expf(loc[i] - mx);
        loc[i] = p;
        s += p;
    }
    #pragma unroll
    for (int o = 16; o > 0; o >>= 1) s += __shfl_xor_sync(0xffffffffu, s, o);
    __syncthreads();
    if (lane == 0) red[wid] = s;
    __syncthreads();
    if (tid == 0) {
        float t = 0.f;
        for (int i = 0; i < 8; i++) t += red[i];
        red[0] = t;
    }
    __syncthreads();
    float inv = 1.0f / red[0];
    #pragma unroll
    for (int i = 0; i < 16; i++)
        out_attn[(size_t)b * TT + i * 256 + tid] = loc[i] * inv;
}

// ---------------- kernel 4: context partials — UNCHANGED (R9 WIN) ----------------
__global__ __launch_bounds__(256)
void ctx_part_kernel(const float* __restrict__ memory, const float* __restrict__ attn) {
    const int tc = blockIdx.x;   // 0..15
    const int b  = blockIdx.y;   // 0..63
    const int tid = threadIdx.x; // 256

    __shared__ float a_s[256];
    a_s[tid] = attn[(size_t)b * TT + tc * 256 + tid];
    __syncthreads();

    const float4* mp = (const float4*)(memory + ((size_t)b * TT + (size_t)tc * 256) * MEM) + tid;

    float4 acc0 = {0.f, 0.f, 0.f, 0.f}, acc1 = {0.f, 0.f, 0.f, 0.f};
    #pragma unroll 4
    for (int t = 0; t < 256; t += 2) {
        float a0 = a_s[t], a1 = a_s[t + 1];
        if (a0 != 0.f) {
            float4 m0 = mp[(size_t)t * 256];
            acc0.x = fmaf(a0, m0.x, acc0.x); acc0.y = fmaf(a0, m0.y, acc0.y);
            acc0.z = fmaf(a0, m0.z, acc0.z); acc0.w = fmaf(a0, m0.w, acc0.w);
        }
        if (a1 != 0.f) {
            float4 m1 = mp[(size_t)(t + 1) * 256];
            acc1.x = fmaf(a1, m1.x, acc1.x); acc1.y = fmaf(a1, m1.y, acc1.y);
            acc1.z = fmaf(a1, m1.z, acc1.z); acc1.w = fmaf(a1, m1.w, acc1.w);
        }
    }
    acc0.x += acc1.x; acc0.y += acc1.y; acc0.z += acc1.z; acc0.w += acc1.w;
    ((float4*)g_ctx)[((size_t)tc * BB + b) * (MEM / 4) + tid] = acc0;
}

// ---------------- kernel 5: reduce 16 partials ----------------
__global__ void ctx_reduce_kernel(float* __restrict__ out_ctx) {
    int idx = blockIdx.x * 256 + threadIdx.x;
    float s = 0.f;
    #pragma unroll
    for (int tc = 0; tc < TCH; tc++) s += g_ctx[tc * (BB * MEM) + idx];
    out_ctx[idx] = s;
}

// ---------------- launch ----------------
extern "C" void kernel_launch(void* const* d_in, const int* in_sizes, int n_in,
                              void* d_out, int out_size) {
    const float* h_t    = (const float*)d_in[0];
    const float* memory = (const float*)d_in[1];
    const void*  mask   = d_in[2];
    const float* w_h    = (const float*)d_in[3];
    const float* w_m    = (const float*)d_in[4];
    const float* v      = (const float*)d_in[5];

    float* out      = (float*)d_out;
    float* out_ctx  = out;                 // [64,1024]
    float* out_attn = out + BB * MEM;      // [64,4096]

    cudaFuncSetAttribute(gemm_e_kernel, cudaFuncAttributeMaxDynamicSharedMemorySize,
                         GEMM_SMEM_BYTES);

    q_kernel<<<2048, 256>>>(h_t, w_h);
    gemm_e_kernel<<<dim3(TT / MT, BB), 256, GEMM_SMEM_BYTES>>>(memory, w_m, v);
    softmax_kernel<<<BB, 256>>>(mask, out_attn);
    ctx_part_kernel<<<dim3(TCH, BB), 256>>>(memory, out_attn);
    ctx_reduce_kernel<<<256, 256>>>(out_ctx);
}

// round 11
// speedup vs baseline: 1.6181x; 1.6181x over previous
#include <cuda_runtime.h>
#include <cuda_fp16.h>
#include <math.h>
#include <stdint.h>

#define BB   64
#define TT   4096
#define HID  1024
#define MEM  1024
#define ATTN 256
#define TCH  16
#define NTILE 18
#define ET   (NTILE * 128)    // 2304 compact rows per batch

// ---------------- device scratch ----------------
__device__ float g_q[BB * ATTN];
__device__ float g_e[BB * ET];
__device__ int   g_idx[BB * ET];
__device__ int   g_cnt[BB];
__device__ float g_ctx[TCH * BB * MEM];

// ---------------- helpers ----------------
__device__ __forceinline__ void cp_async16(void* smem, const void* gmem) {
    unsigned s = (unsigned)__cvta_generic_to_shared(smem);
    asm volatile("cp.async.cg.shared.global [%0], [%1], 16;\n" :: "r"(s), "l"(gmem));
}
__device__ __forceinline__ void cp_commit() {
    asm volatile("cp.async.commit_group;\n");
}
template<int N>
__device__ __forceinline__ void cp_wait() {
    asm volatile("cp.async.wait_group %0;\n" :: "n"(N));
}
__device__ __forceinline__ uint32_t pack_h2(float x, float y) {
    uint32_t r;
    asm("cvt.rn.f16x2.f32 %0, %2, %1;" : "=r"(r) : "f"(x), "f"(y));
    return r;
}
__device__ __forceinline__ void mma_f16(float* c, const uint32_t* a, const uint32_t* b) {
    asm volatile(
        "mma.sync.aligned.m16n8k16.row.col.f32.f16.f16.f32 "
        "{%0,%1,%2,%3}, {%4,%5,%6,%7}, {%8,%9}, {%0,%1,%2,%3};"
        : "+f"(c[0]), "+f"(c[1]), "+f"(c[2]), "+f"(c[3])
        : "r"(a[0]), "r"(a[1]), "r"(a[2]), "r"(a[3]), "r"(b[0]), "r"(b[1]));
}
__device__ __forceinline__ float tanh_acc(float x) {
    float e2 = __expf(2.0f * x);
    return 1.0f - __fdividef(2.0f, e2 + 1.0f);
}

// ---------------- kernel 1: q = h_t @ w_h^T ----------------
__global__ void q_kernel(const float* __restrict__ h_t, const float* __restrict__ w_h) {
    int g = blockIdx.x * 8 + (threadIdx.x >> 5);
    int lane = threadIdx.x & 31;
    int b = g >> 8, a = g & 255;
    const float4* hp = (const float4*)(h_t + (size_t)b * HID);
    const float4* wp = (const float4*)(w_h + (size_t)a * HID);
    float s = 0.f;
    #pragma unroll
    for (int i = lane; i < 256; i += 32) {
        float4 h4 = hp[i], w4 = wp[i];
        s += h4.x * w4.x + h4.y * w4.y + h4.z * w4.z + h4.w * w4.w;
    }
    #pragma unroll
    for (int o = 16; o > 0; o >>= 1) s += __shfl_xor_sync(0xffffffffu, s, o);
    if (lane == 0) g_q[b * ATTN + a] = s;
}

// ---------------- kernel 1b: compact unmasked indices per batch ----------------
__global__ void idx_kernel(const void* __restrict__ maskp) {
    const int b = blockIdx.x, tid = threadIdx.x;
    __shared__ int flag;
    __shared__ int wsum[8];
    __shared__ int ntot_s;
    if (tid == 0) flag = 0;
    __syncthreads();
    const int* mi32 = (const int*)maskp;
    if (tid < 64) {
        unsigned w = (unsigned)mi32[tid];
        if (w > 1u) atomicOr(&flag, 1);
    }
    __syncthreads();
    const bool bytes = (flag != 0);
    const unsigned char* mu8 = (const unsigned char*)maskp;

    // each thread: 16 consecutive t
    uint32_t bits = 0;
    #pragma unroll
    for (int i = 0; i < 16; i++) {
        int t = tid * 16 + i;
        bool m = bytes ? (mu8[(size_t)b * TT + t] != 0) : (mi32[(size_t)b * TT + t] != 0);
        bits |= (m ? 1u : 0u) << i;
    }
    int cnt = __popc(bits);

    // block exclusive scan
    int lane = tid & 31, w = tid >> 5;
    int incl = cnt;
    #pragma unroll
    for (int o = 1; o < 32; o <<= 1) {
        int v = __shfl_up_sync(0xffffffffu, incl, o);
        if (lane >= o) incl += v;
    }
    if (lane == 31) wsum[w] = incl;
    __syncthreads();
    int woff = 0;
    for (int i = 0; i < w; i++) woff += wsum[i];
    int excl = woff + incl - cnt;
    if (tid == 255) ntot_s = woff + incl;
    __syncthreads();
    int ntot = ntot_s;

    int p = excl;
    #pragma unroll
    for (int i = 0; i < 16; i++)
        if ((bits >> i) & 1) g_idx[b * ET + p++] = tid * 16 + i;
    for (int i = ntot + tid; i < ET; i += 256) g_idx[b * ET + i] = 0;  // pad
    if (tid == 0) g_cnt[b] = ntot;
}

// ---------------- kernel 2: fused e-GEMM (R9 shape, gathered rows) ----------------
#define AS_STRIDE 40
#define A_BUF (128 * AS_STRIDE)
#define B_BUF (256 * AS_STRIDE)
#define GEMM_SMEM_BYTES ((2 * A_BUF + 2 * B_BUF) * 4)

__global__ __launch_bounds__(256, 1)
void gemm_e_kernel(const float* __restrict__ memory, const float* __restrict__ w_m,
                   const float* __restrict__ v) {
    extern __shared__ float sm[];
    float* As = sm;               // [2][128][40]
    float* Bsm = sm + 2 * A_BUF;  // [2][256][40]
    __shared__ float q_s[ATTN];
    __shared__ float v_s[ATTN];
    __shared__ float e_s[4][128];
    __shared__ int tix[128];

    const int tid = threadIdx.x;
    const int b = blockIdx.y;
    const int t0 = blockIdx.x * 128;

    q_s[tid] = g_q[b * ATTN + tid];
    v_s[tid] = v[tid];
    if (tid < 128) tix[tid] = g_idx[b * ET + t0 + tid];
    __syncthreads();

    // per-thread fixed A row pointers (gathered)
    const float* aptr[4];
    {
        int colb = (tid & 7) * 4;
        #pragma unroll
        for (int i = 0; i < 4; i++) {
            int r = i * 32 + (tid >> 3);
            aptr[i] = memory + ((size_t)b * TT + tix[r]) * MEM + colb;
        }
    }
    const float* Bg = w_m;

    auto stage = [&](int kc, int bf) {
        #pragma unroll
        for (int i = 0; i < 4; i++) {
            int idx = i * 256 + tid;
            int r = idx >> 3, c = (idx & 7) * 4;
            cp_async16(&As[bf * A_BUF + r * AS_STRIDE + c], aptr[i] + kc * 32);
        }
        const float* bg = Bg + kc * 32;
        #pragma unroll
        for (int i = 0; i < 8; i++) {
            int idx = i * 256 + tid;
            int r = idx >> 3, c = (idx & 7) * 4;
            cp_async16(&Bsm[bf * B_BUF + r * AS_STRIDE + c], bg + (size_t)r * MEM + c);
        }
    };

    const int warp = tid >> 5, lane = tid & 31;
    const int wm = warp >> 2, wn = warp & 3;
    const int gid = lane >> 2, tig = lane & 3;

    float acc[4][8][4];
    #pragma unroll
    for (int mi = 0; mi < 4; mi++)
        #pragma unroll
        for (int ni = 0; ni < 8; ni++)
            #pragma unroll
            for (int j = 0; j < 4; j++) acc[mi][ni][j] = 0.f;

    int buf = 0;
    stage(0, 0);
    cp_commit();

    for (int kc = 0; kc < 32; kc++) {
        if (kc + 1 < 32) { stage(kc + 1, buf ^ 1); cp_commit(); cp_wait<1>(); }
        else             { cp_wait<0>(); }
        __syncthreads();

        const float* A = &As[buf * A_BUF];
        const float* Bs = &Bsm[buf * B_BUF];
        #pragma unroll
        for (int kw = 0; kw < 32; kw += 16) {
            uint32_t af[4][4], bf[8][2];
            #pragma unroll
            for (int mi = 0; mi < 4; mi++) {
                int r = wm * 64 + mi * 16 + gid;
                float2 f0 = *(const float2*)(A + r * AS_STRIDE + kw + 2 * tig);
                float2 f1 = *(const float2*)(A + (r + 8) * AS_STRIDE + kw + 2 * tig);
                float2 f2 = *(const float2*)(A + r * AS_STRIDE + kw + 2 * tig + 8);
                float2 f3 = *(const float2*)(A + (r + 8) * AS_STRIDE + kw + 2 * tig + 8);
                af[mi][0] = pack_h2(f0.x, f0.y);
                af[mi][1] = pack_h2(f1.x, f1.y);
                af[mi][2] = pack_h2(f2.x, f2.y);
                af[mi][3] = pack_h2(f3.x, f3.y);
            }
            #pragma unroll
            for (int ni = 0; ni < 8; ni++) {
                int c = wn * 64 + ni * 8 + gid;
                float2 f0 = *(const float2*)(Bs + c * AS_STRIDE + kw + 2 * tig);
                float2 f1 = *(const float2*)(Bs + c * AS_STRIDE + kw + 2 * tig + 8);
                bf[ni][0] = pack_h2(f0.x, f0.y);
                bf[ni][1] = pack_h2(f1.x, f1.y);
            }
            #pragma unroll
            for (int mi = 0; mi < 4; mi++)
                #pragma unroll
                for (int ni = 0; ni < 8; ni++)
                    mma_f16(acc[mi][ni], af[mi], bf[ni]);
        }
        __syncthreads();
        buf ^= 1;
    }

    #pragma unroll
    for (int mi = 0; mi < 4; mi++) {
        float s0 = 0.f, s1 = 0.f;
        #pragma unroll
        for (int ni = 0; ni < 8; ni++) {
            int c0 = wn * 64 + ni * 8 + 2 * tig;
            s0 += v_s[c0]     * tanh_acc(q_s[c0]     + acc[mi][ni][0]);
            s0 += v_s[c0 + 1] * tanh_acc(q_s[c0 + 1] + acc[mi][ni][1]);
            s1 += v_s[c0]     * tanh_acc(q_s[c0]     + acc[mi][ni][2]);
            s1 += v_s[c0 + 1] * tanh_acc(q_s[c0 + 1] + acc[mi][ni][3]);
        }
        s0 += __shfl_xor_sync(0xffffffffu, s0, 1);
        s0 += __shfl_xor_sync(0xffffffffu, s0, 2);
        s1 += __shfl_xor_sync(0xffffffffu, s1, 1);
        s1 += __shfl_xor_sync(0xffffffffu, s1, 2);
        if (tig == 0) {
            e_s[wn][wm * 64 + mi * 16 + gid]     = s0;
            e_s[wn][wm * 64 + mi * 16 + gid + 8] = s1;
        }
    }
    __syncthreads();
    if (tid < 128) {
        float e = e_s[0][tid] + e_s[1][tid] + e_s[2][tid] + e_s[3][tid];
        g_e[(size_t)b * ET + t0 + tid] = e;
    }
}

// ---------------- kernel 3: softmax over compact e, scatter ----------------
__global__ void softmax_kernel(float* __restrict__ out_attn) {
    const int b = blockIdx.x, tid = threadIdx.x;
    __shared__ float red[8];

    // zero full attn row
    #pragma unroll
    for (int i = 0; i < 16; i++) out_attn[(size_t)b * TT + i * 256 + tid] = 0.f;

    const int n = g_cnt[b];
    float loc[9];
    float mx = -INFINITY;
    #pragma unroll
    for (int i = 0; i < 9; i++) {
        int j = i * 256 + tid;
        float e = (j < n) ? g_e[(size_t)b * ET + j] : -INFINITY;
        loc[i] = e;
        mx = fmaxf(mx, e);
    }
    int lane = tid & 31, wid = tid >> 5;
    #pragma unroll
    for (int o = 16; o > 0; o >>= 1) mx = fmaxf(mx, __shfl_xor_sync(0xffffffffu, mx, o));
    if (lane == 0) red[wid] = mx;
    __syncthreads();
    if (tid == 0) {
        float m = red[0];
        for (int i = 1; i < 8; i++) m = fmaxf(m, red[i]);
        red[0] = m;
    }
    __syncthreads();
    mx = red[0];

    float s = 0.f;
    #pragma unroll
    for (int i = 0; i < 9; i++) {
        float p = __expf(loc[i] - mx);
        loc[i] = p;
        s += p;
    }
    #pragma unroll
    for (int o = 16; o > 0; o >>= 1) s += __shfl_xor_sync(0xffffffffu, s, o);
    __syncthreads();
    if (lane == 0) red[wid] = s;
    __syncthreads();
    if (tid == 0) {
        float t = 0.f;
        for (int i = 0; i < 8; i++) t += red[i];
        red[0] = t;
    }
    __syncthreads();
    float inv = 1.0f / red[0];

    // scatter (zero-fill is ordered before this by the reduction syncs)
    #pragma unroll
    for (int i = 0; i < 9; i++) {
        int j = i * 256 + tid;
        if (j < n) out_attn[(size_t)b * TT + g_idx[b * ET + j]] = loc[i] * inv;
    }
}

// ---------------- kernel 4: context partials — UNCHANGED (R9 WIN) ----------------
__global__ __launch_bounds__(256)
void ctx_part_kernel(const float* __restrict__ memory, const float* __restrict__ attn) {
    const int tc = blockIdx.x;
    const int b  = blockIdx.y;
    const int tid = threadIdx.x;

    __shared__ float a_s[256];
    a_s[tid] = attn[(size_t)b * TT + tc * 256 + tid];
    __syncthreads();

    const float4* mp = (const float4*)(memory + ((size_t)b * TT + (size_t)tc * 256) * MEM) + tid;

    float4 acc0 = {0.f, 0.f, 0.f, 0.f}, acc1 = {0.f, 0.f, 0.f, 0.f};
    #pragma unroll 4
    for (int t = 0; t < 256; t += 2) {
        float a0 = a_s[t], a1 = a_s[t + 1];
        if (a0 != 0.f) {
            float4 m0 = mp[(size_t)t * 256];
            acc0.x = fmaf(a0, m0.x, acc0.x); acc0.y = fmaf(a0, m0.y, acc0.y);
            acc0.z = fmaf(a0, m0.z, acc0.z); acc0.w = fmaf(a0, m0.w, acc0.w);
        }
        if (a1 != 0.f) {
            float4 m1 = mp[(size_t)(t + 1) * 256];
            acc1.x = fmaf(a1, m1.x, acc1.x); acc1.y = fmaf(a1, m1.y, acc1.y);
            acc1.z = fmaf(a1, m1.z, acc1.z); acc1.w = fmaf(a1, m1.w, acc1.w);
        }
    }
    acc0.x += acc1.x; acc0.y += acc1.y; acc0.z += acc1.z; acc0.w += acc1.w;
    ((float4*)g_ctx)[((size_t)tc * BB + b) * (MEM / 4) + tid] = acc0;
}

// ---------------- kernel 5: reduce 16 partials ----------------
__global__ void ctx_reduce_kernel(float* __restrict__ out_ctx) {
    int idx = blockIdx.x * 256 + threadIdx.x;
    float s = 0.f;
    #pragma unroll
    for (int tc = 0; tc < TCH; tc++) s += g_ctx[tc * (BB * MEM) + idx];
    out_ctx[idx] = s;
}

// ---------------- launch ----------------
extern "C" void kernel_launch(void* const* d_in, const int* in_sizes, int n_in,
                              void* d_out, int out_size) {
    const float* h_t    = (const float*)d_in[0];
    const float* memory = (const float*)d_in[1];
    const void*  mask   = d_in[2];
    const float* w_h    = (const float*)d_in[3];
    const float* w_m    = (const float*)d_in[4];
    const float* v      = (const float*)d_in[5];

    float* out      = (float*)d_out;
    float* out_ctx  = out;                 // [64,1024]
    float* out_attn = out + BB * MEM;      // [64,4096]

    cudaFuncSetAttribute(gemm_e_kernel, cudaFuncAttributeMaxDynamicSharedMemorySize,
                         GEMM_SMEM_BYTES);

    q_kernel<<<2048, 256>>>(h_t, w_h);
    idx_kernel<<<BB, 256>>>(mask);
    gemm_e_kernel<<<dim3(NTILE, BB), 256, GEMM_SMEM_BYTES>>>(memory, w_m, v);
    softmax_kernel<<<BB, 256>>>(out_attn);
    ctx_part_kernel<<<dim3(TCH, BB), 256>>>(memory, out_attn);
    ctx_reduce_kernel<<<256, 256>>>(out_ctx);
}

// round 13
// speedup vs baseline: 1.6182x; 1.0001x over previous
#include <cuda_runtime.h>
#include <cuda_fp16.h>
#include <math.h>
#include <stdint.h>

#define BB   64
#define TT   4096
#define HID  1024
#define MEM  1024
#define ATTN 256
#define TCH  16
#define NTILE 18
#define ET   (NTILE * 128)    // 2304 compact rows per batch

// ---------------- device scratch ----------------
__device__ float g_q[BB * ATTN];
__device__ float g_e[BB * ET];
__device__ int   g_idx[BB * ET];
__device__ int   g_cnt[BB];
__device__ float g_ctx[TCH * BB * MEM];

// ---------------- helpers ----------------
__device__ __forceinline__ void cp_async16(void* smem, const void* gmem) {
    unsigned s = (unsigned)__cvta_generic_to_shared(smem);
    asm volatile("cp.async.cg.shared.global [%0], [%1], 16;\n" :: "r"(s), "l"(gmem));
}
__device__ __forceinline__ void cp_commit() {
    asm volatile("cp.async.commit_group;\n");
}
template<int N>
__device__ __forceinline__ void cp_wait() {
    asm volatile("cp.async.wait_group %0;\n" :: "n"(N));
}
__device__ __forceinline__ uint32_t pack_h2(float x, float y) {
    uint32_t r;
    asm("cvt.rn.f16x2.f32 %0, %2, %1;" : "=r"(r) : "f"(x), "f"(y));
    return r;
}
__device__ __forceinline__ void mma_f16(float* c, const uint32_t* a, const uint32_t* b) {
    asm volatile(
        "mma.sync.aligned.m16n8k16.row.col.f32.f16.f16.f32 "
        "{%0,%1,%2,%3}, {%4,%5,%6,%7}, {%8,%9}, {%0,%1,%2,%3};"
        : "+f"(c[0]), "+f"(c[1]), "+f"(c[2]), "+f"(c[3])
        : "r"(a[0]), "r"(a[1]), "r"(a[2]), "r"(a[3]), "r"(b[0]), "r"(b[1]));
}
__device__ __forceinline__ float tanh_acc(float x) {
    float e2 = __expf(2.0f * x);
    return 1.0f - __fdividef(2.0f, e2 + 1.0f);
}

// ---------------- kernel 1: q = h_t @ w_h^T ----------------
__global__ void q_kernel(const float* __restrict__ h_t, const float* __restrict__ w_h) {
    int g = blockIdx.x * 8 + (threadIdx.x >> 5);
    int lane = threadIdx.x & 31;
    int b = g >> 8, a = g & 255;
    const float4* hp = (const float4*)(h_t + (size_t)b * HID);
    const float4* wp = (const float4*)(w_h + (size_t)a * HID);
    float s = 0.f;
    #pragma unroll
    for (int i = lane; i < 256; i += 32) {
        float4 h4 = hp[i], w4 = wp[i];
        s += h4.x * w4.x + h4.y * w4.y + h4.z * w4.z + h4.w * w4.w;
    }
    #pragma unroll
    for (int o = 16; o > 0; o >>= 1) s += __shfl_xor_sync(0xffffffffu, s, o);
    if (lane == 0) g_q[b * ATTN + a] = s;
}

// ---------------- kernel 1b: compact unmasked indices per batch ----------------
__global__ void idx_kernel(const void* __restrict__ maskp) {
    const int b = blockIdx.x, tid = threadIdx.x;
    __shared__ int flag;
    __shared__ int wsum[8];
    __shared__ int ntot_s;
    if (tid == 0) flag = 0;
    __syncthreads();
    const int* mi32 = (const int*)maskp;
    if (tid < 64) {
        unsigned w = (unsigned)mi32[tid];
        if (w > 1u) atomicOr(&flag, 1);
    }
    __syncthreads();
    const bool bytes = (flag != 0);
    const unsigned char* mu8 = (const unsigned char*)maskp;

    uint32_t bits = 0;
    #pragma unroll
    for (int i = 0; i < 16; i++) {
        int t = tid * 16 + i;
        bool m = bytes ? (mu8[(size_t)b * TT + t] != 0) : (mi32[(size_t)b * TT + t] != 0);
        bits |= (m ? 1u : 0u) << i;
    }
    int cnt = __popc(bits);

    int lane = tid & 31, w = tid >> 5;
    int incl = cnt;
    #pragma unroll
    for (int o = 1; o < 32; o <<= 1) {
        int v = __shfl_up_sync(0xffffffffu, incl, o);
        if (lane >= o) incl += v;
    }
    if (lane == 31) wsum[w] = incl;
    __syncthreads();
    int woff = 0;
    for (int i = 0; i < w; i++) woff += wsum[i];
    int excl = woff + incl - cnt;
    if (tid == 255) ntot_s = woff + incl;
    __syncthreads();
    int ntot = ntot_s;

    int p = excl;
    #pragma unroll
    for (int i = 0; i < 16; i++)
        if ((bits >> i) & 1) g_idx[b * ET + p++] = tid * 16 + i;
    for (int i = ntot + tid; i < ET; i += 256) g_idx[b * ET + i] = 0;
    if (tid == 0) g_cnt[b] = ntot;
}

// ---------------- kernel 2: fused e-GEMM (gathered rows, empty-tile early exit) ----------------
#define AS_STRIDE 40
#define A_BUF (128 * AS_STRIDE)
#define B_BUF (256 * AS_STRIDE)
#define GEMM_SMEM_BYTES ((2 * A_BUF + 2 * B_BUF) * 4)

__global__ __launch_bounds__(256, 1)
void gemm_e_kernel(const float* __restrict__ memory, const float* __restrict__ w_m,
                   const float* __restrict__ v) {
    extern __shared__ float sm[];
    float* As = sm;               // [2][128][40]
    float* Bsm = sm + 2 * A_BUF;  // [2][256][40]
    __shared__ float q_s[ATTN];
    __shared__ float v_s[ATTN];
    __shared__ float e_s[4][128];
    __shared__ int tix[128];

    const int tid = threadIdx.x;
    const int b = blockIdx.y;
    const int t0 = blockIdx.x * 128;

    // early exit: entire tile is padding (uniform across CTA)
    if (t0 >= g_cnt[b]) return;

    q_s[tid] = g_q[b * ATTN + tid];
    v_s[tid] = v[tid];
    if (tid < 128) tix[tid] = g_idx[b * ET + t0 + tid];
    __syncthreads();

    const float* aptr[4];
    {
        int colb = (tid & 7) * 4;
        #pragma unroll
        for (int i = 0; i < 4; i++) {
            int r = i * 32 + (tid >> 3);
            aptr[i] = memory + ((size_t)b * TT + tix[r]) * MEM + colb;
        }
    }
    const float* Bg = w_m;

    auto stage = [&](int kc, int bf) {
        #pragma unroll
        for (int i = 0; i < 4; i++) {
            int idx = i * 256 + tid;
            int r = idx >> 3, c = (idx & 7) * 4;
            cp_async16(&As[bf * A_BUF + r * AS_STRIDE + c], aptr[i] + kc * 32);
        }
        const float* bg = Bg + kc * 32;
        #pragma unroll
        for (int i = 0; i < 8; i++) {
            int idx = i * 256 + tid;
            int r = idx >> 3, c = (idx & 7) * 4;
            cp_async16(&Bsm[bf * B_BUF + r * AS_STRIDE + c], bg + (size_t)r * MEM + c);
        }
    };

    const int warp = tid >> 5, lane = tid & 31;
    const int wm = warp >> 2, wn = warp & 3;
    const int gid = lane >> 2, tig = lane & 3;

    float acc[4][8][4];
    #pragma unroll
    for (int mi = 0; mi < 4; mi++)
        #pragma unroll
        for (int ni = 0; ni < 8; ni++)
            #pragma unroll
            for (int j = 0; j < 4; j++) acc[mi][ni][j] = 0.f;

    int buf = 0;
    stage(0, 0);
    cp_commit();

    for (int kc = 0; kc < 32; kc++) {
        if (kc + 1 < 32) { stage(kc + 1, buf ^ 1); cp_commit(); cp_wait<1>(); }
        else             { cp_wait<0>(); }
        __syncthreads();

        const float* A = &As[buf * A_BUF];
        const float* Bs = &Bsm[buf * B_BUF];
        #pragma unroll
        for (int kw = 0; kw < 32; kw += 16) {
            uint32_t af[4][4], bf[8][2];
            #pragma unroll
            for (int mi = 0; mi < 4; mi++) {
                int r = wm * 64 + mi * 16 + gid;
                float2 f0 = *(const float2*)(A + r * AS_STRIDE + kw + 2 * tig);
                float2 f1 = *(const float2*)(A + (r + 8) * AS_STRIDE + kw + 2 * tig);
                float2 f2 = *(const float2*)(A + r * AS_STRIDE + kw + 2 * tig + 8);
                float2 f3 = *(const float2*)(A + (r + 8) * AS_STRIDE + kw + 2 * tig + 8);
                af[mi][0] = pack_h2(f0.x, f0.y);
                af[mi][1] = pack_h2(f1.x, f1.y);
                af[mi][2] = pack_h2(f2.x, f2.y);
                af[mi][3] = pack_h2(f3.x, f3.y);
            }
            #pragma unroll
            for (int ni = 0; ni < 8; ni++) {
                int c = wn * 64 + ni * 8 + gid;
                float2 f0 = *(const float2*)(Bs + c * AS_STRIDE + kw + 2 * tig);
                float2 f1 = *(const float2*)(Bs + c * AS_STRIDE + kw + 2 * tig + 8);
                bf[ni][0] = pack_h2(f0.x, f0.y);
                bf[ni][1] = pack_h2(f1.x, f1.y);
            }
            #pragma unroll
            for (int mi = 0; mi < 4; mi++)
                #pragma unroll
                for (int ni = 0; ni < 8; ni++)
                    mma_f16(acc[mi][ni], af[mi], bf[ni]);
        }
        __syncthreads();
        buf ^= 1;
    }

    #pragma unroll
    for (int mi = 0; mi < 4; mi++) {
        float s0 = 0.f, s1 = 0.f;
        #pragma unroll
        for (int ni = 0; ni < 8; ni++) {
            int c0 = wn * 64 + ni * 8 + 2 * tig;
            s0 += v_s[c0]     * tanh_acc(q_s[c0]     + acc[mi][ni][0]);
            s0 += v_s[c0 + 1] * tanh_acc(q_s[c0 + 1] + acc[mi][ni][1]);
            s1 += v_s[c0]     * tanh_acc(q_s[c0]     + acc[mi][ni][2]);
            s1 += v_s[c0 + 1] * tanh_acc(q_s[c0 + 1] + acc[mi][ni][3]);
        }
        s0 += __shfl_xor_sync(0xffffffffu, s0, 1);
        s0 += __shfl_xor_sync(0xffffffffu, s0, 2);
        s1 += __shfl_xor_sync(0xffffffffu, s1, 1);
        s1 += __shfl_xor_sync(0xffffffffu, s1, 2);
        if (tig == 0) {
            e_s[wn][wm * 64 + mi * 16 + gid]     = s0;
            e_s[wn][wm * 64 + mi * 16 + gid + 8] = s1;
        }
    }
    __syncthreads();
    if (tid < 128) {
        float e = e_s[0][tid] + e_s[1][tid] + e_s[2][tid] + e_s[3][tid];
        g_e[(size_t)b * ET + t0 + tid] = e;
    }
}

// ---------------- kernel 3: softmax over compact e, scatter ----------------
__global__ void softmax_kernel(float* __restrict__ out_attn) {
    const int b = blockIdx.x, tid = threadIdx.x;
    __shared__ float red[8];

    #pragma unroll
    for (int i = 0; i < 16; i++) out_attn[(size_t)b * TT + i * 256 + tid] = 0.f;

    const int n = g_cnt[b];
    float loc[9];
    float mx = -INFINITY;
    #pragma unroll
    for (int i = 0; i < 9; i++) {
        int j = i * 256 + tid;
        float e = (j < n) ? g_e[(size_t)b * ET + j] : -INFINITY;
        loc[i] = e;
        mx = fmaxf(mx, e);
    }
    int lane = tid & 31, wid = tid >> 5;
    #pragma unroll
    for (int o = 16; o > 0; o >>= 1) mx = fmaxf(mx, __shfl_xor_sync(0xffffffffu, mx, o));
    if (lane == 0) red[wid] = mx;
    __syncthreads();
    if (tid == 0) {
        float m = red[0];
        for (int i = 1; i < 8; i++) m = fmaxf(m, red[i]);
        red[0] = m;
    }
    __syncthreads();
    mx = red[0];

    float s = 0.f;
    #pragma unroll
    for (int i = 0; i < 9; i++) {
        float p = __expf(loc[i] - mx);
        loc[i] = p;
        s += p;
    }
    #pragma unroll
    for (int o = 16; o > 0; o >>= 1) s += __shfl_xor_sync(0xffffffffu, s, o);
    __syncthreads();
    if (lane == 0) red[wid] = s;
    __syncthreads();
    if (tid == 0) {
        float t = 0.f;
        for (int i = 0; i < 8; i++) t += red[i];
        red[0] = t;
    }
    __syncthreads();
    float inv = 1.0f / red[0];

    #pragma unroll
    for (int i = 0; i < 9; i++) {
        int j = i * 256 + tid;
        if (j < n) out_attn[(size_t)b * TT + g_idx[b * ET + j]] = loc[i] * inv;
    }
}

// ---------------- kernel 4: context partials (unroll 8) ----------------
__global__ __launch_bounds__(256)
void ctx_part_kernel(const float* __restrict__ memory, const float* __restrict__ attn) {
    const int tc = blockIdx.x;
    const int b  = blockIdx.y;
    const int tid = threadIdx.x;

    __shared__ float a_s[256];
    a_s[tid] = attn[(size_t)b * TT + tc * 256 + tid];
    __syncthreads();

    const float4* mp = (const float4*)(memory + ((size_t)b * TT + (size_t)tc * 256) * MEM) + tid;

    float4 acc0 = {0.f, 0.f, 0.f, 0.f}, acc1 = {0.f, 0.f, 0.f, 0.f};
    #pragma unroll 8
    for (int t = 0; t < 256; t += 2) {
        float a0 = a_s[t], a1 = a_s[t + 1];
        if (a0 != 0.f) {
            float4 m0 = mp[(size_t)t * 256];
            acc0.x = fmaf(a0, m0.x, acc0.x); acc0.y = fmaf(a0, m0.y, acc0.y);
            acc0.z = fmaf(a0, m0.z, acc0.z); acc0.w = fmaf(a0, m0.w, acc0.w);
        }
        if (a1 != 0.f) {
            float4 m1 = mp[(size_t)(t + 1) * 256];
            acc1.x = fmaf(a1, m1.x, acc1.x); acc1.y = fmaf(a1, m1.y, acc1.y);
            acc1.z = fmaf(a1, m1.z, acc1.z); acc1.w = fmaf(a1, m1.w, acc1.w);
        }
    }
    acc0.x += acc1.x; acc0.y += acc1.y; acc0.z += acc1.z; acc0.w += acc1.w;
    ((float4*)g_ctx)[((size_t)tc * BB + b) * (MEM / 4) + tid] = acc0;
}

// ---------------- kernel 5: reduce 16 partials ----------------
__global__ void ctx_reduce_kernel(float* __restrict__ out_ctx) {
    int idx = blockIdx.x * 256 + threadIdx.x;
    float s = 0.f;
    #pragma unroll
    for (int tc = 0; tc < TCH; tc++) s += g_ctx[tc * (BB * MEM) + idx];
    out_ctx[idx] = s;
}

// ---------------- launch ----------------
extern "C" void kernel_launch(void* const* d_in, const int* in_sizes, int n_in,
                              void* d_out, int out_size) {
    const float* h_t    = (const float*)d_in[0];
    const float* memory = (const float*)d_in[1];
    const void*  mask   = d_in[2];
    const float* w_h    = (const float*)d_in[3];
    const float* w_m    = (const float*)d_in[4];
    const float* v      = (const float*)d_in[5];

    float* out      = (float*)d_out;
    float* out_ctx  = out;                 // [64,1024]
    float* out_attn = out + BB * MEM;      // [64,4096]

    cudaFuncSetAttribute(gemm_e_kernel, cudaFuncAttributeMaxDynamicSharedMemorySize,
                         GEMM_SMEM_BYTES);

    q_kernel<<<2048, 256>>>(h_t, w_h);
    idx_kernel<<<BB, 256>>>(mask);
    gemm_e_kernel<<<dim3(NTILE, BB), 256, GEMM_SMEM_BYTES>>>(memory, w_m, v);
    softmax_kernel<<<BB, 256>>>(out_attn);
    ctx_part_kernel<<<dim3(TCH, BB), 256>>>(memory, out_attn);
    ctx_reduce_kernel<<<256, 256>>>(out_ctx);
}